// round 8
// baseline (speedup 1.0000x reference)
#include <cuda_runtime.h>
#include <cuda_fp16.h>
#include <cstdint>
#include <cstddef>

#define B_SZ   8192
#define C_SZ   12
#define DIN    1024
#define DOUT   1024
#define N_COLS (C_SZ * DOUT)   // 12288
#define A_SZ   8

// Scratch (static device allocations allowed)
__device__ float  g_u[(size_t)B_SZ * N_COLS];    // 402 MB
__device__ float  g_ent[B_SZ];
__device__ __half g_xh[(size_t)B_SZ * DIN];
__device__ __half g_xl[(size_t)B_SZ * DIN];
__device__ __half g_wh[(size_t)N_COLS * DIN];    // W * 32, hi
__device__ __half g_wl[(size_t)N_COLS * DIN];    // W * 32, lo

#define W_SCALE     32.0f
#define W_SCALE_INV 0.03125f

// ------------------------------ split precompute ------------------------------
__device__ __forceinline__ void sp1(float x, __half& h, __half& l) {
    h = __float2half_rn(x);
    l = __float2half_rn(x - __half2float(h));
}

__global__ void __launch_bounds__(256)
split_kernel(const float* __restrict__ src, __half* __restrict__ hi,
             __half* __restrict__ lo, float scale, int n4)
{
    const int i = blockIdx.x * 256 + threadIdx.x;
    if (i >= n4) return;
    const float4 v = *(const float4*)(src + (size_t)i * 4);
    __half h0,h1,h2,h3,l0,l1,l2,l3;
    sp1(v.x * scale, h0, l0); sp1(v.y * scale, h1, l1);
    sp1(v.z * scale, h2, l2); sp1(v.w * scale, h3, l3);
    __half2* hp = (__half2*)(hi + (size_t)i * 4);
    __half2* lp = (__half2*)(lo + (size_t)i * 4);
    hp[0] = __halves2half2(h0, h1); hp[1] = __halves2half2(h2, h3);
    lp[0] = __halves2half2(l0, l1); lp[1] = __halves2half2(l2, l3);
}

// ------------------------------ GEMM ------------------------------
// u[b,co] = (1/32) * sum_i (xh+xl)[b,i]*(wh+wl)[co,i] + bias[co]
// acc += xl*wh + xh*wl + xh*wh   (3x fp16 MMA, fp32 accum)
// 256 threads, 8 warps: 2(M) x 4(N), warp tile 64x32. BK=32, 2-stage, 2 CTAs/SM.
#define BM 128
#define BN 128
#define BK 32
#define NCHUNK (DIN / BK)       // 32
#define PKH 40                  // halves per row (80 B stride, LDSM conflict-free)
#define PLANEH (BM * PKH)       // 5120 halves
#define STAGEH (4 * PLANEH)     // AH, AL, BH, BL
#define SMEM_BYTES (2 * STAGEH * 2)   // 81920 B -> 2 CTAs/SM

__device__ __forceinline__ uint32_t s2u(const void* p) {
    return (uint32_t)__cvta_generic_to_shared(p);
}
__device__ __forceinline__ void cp16(const __half* s, const __half* g) {
    asm volatile("cp.async.cg.shared.global [%0], [%1], 16;\n"
                 :: "r"(s2u(s)), "l"(g));
}
__device__ __forceinline__ void ldsm4(uint32_t r[4], const __half* p) {
    asm volatile("ldmatrix.sync.aligned.m8n8.x4.shared.b16 {%0,%1,%2,%3}, [%4];"
                 : "=r"(r[0]), "=r"(r[1]), "=r"(r[2]), "=r"(r[3]) : "r"(s2u(p)));
}
__device__ __forceinline__ void mma_f16(float acc[4], const uint32_t a[4], const uint32_t* b) {
    asm volatile(
        "mma.sync.aligned.m16n8k16.row.col.f32.f16.f16.f32 "
        "{%0,%1,%2,%3}, {%4,%5,%6,%7}, {%8,%9}, {%0,%1,%2,%3};\n"
        : "+f"(acc[0]), "+f"(acc[1]), "+f"(acc[2]), "+f"(acc[3])
        : "r"(a[0]), "r"(a[1]), "r"(a[2]), "r"(a[3]), "r"(b[0]), "r"(b[1]));
}

__global__ void __launch_bounds__(256, 2)
gemm_fp16_kernel(const float* __restrict__ bias)
{
    extern __shared__ __half smh[];

    const int tid  = threadIdx.x;
    const int lane = tid & 31;
    const int warp = tid >> 5;          // 0..7
    const int wm = warp >> 2;           // 0..1 (M: 64 rows each)
    const int wn = warp & 3;            // 0..3 (N: 32 cols each)
    const int bm = blockIdx.y * BM;
    const int bn = blockIdx.x * BN;

    // producer: per plane 128 rows x 2 16B-chunks; thread -> row tid>>2 (+64), c4 = tid&3
    const int prow = tid >> 2;          // 0..63
    const int pc4  = tid & 3;           // 0..3
    const __half* gx = g_xh + (size_t)(bm + prow) * DIN + pc4 * 8;
    const __half* gw = g_wh + (size_t)(bn + prow) * DIN + pc4 * 8;
    const size_t XL = (size_t)(g_xl - g_xh);   // plane offsets in elements
    const size_t WL = (size_t)(g_wl - g_wh);
    const int soff = prow * PKH + pc4 * 8;
    const size_t rstep = (size_t)64 * DIN;
    const int sstep = 64 * PKH;

    float acc[4][4][4];
    #pragma unroll
    for (int mi = 0; mi < 4; mi++)
        #pragma unroll
        for (int ni = 0; ni < 4; ni++)
            #pragma unroll
            for (int r = 0; r < 4; r++) acc[mi][ni][r] = 0.f;

    // prologue: chunk 0 -> buffer 0
    {
        __half* st = smh;
        #pragma unroll
        for (int i = 0; i < 2; i++) {
            cp16(st + soff + i * sstep,              gx + i * rstep);
            cp16(st + PLANEH + soff + i * sstep,     gx + XL + i * rstep);
            cp16(st + 2 * PLANEH + soff + i * sstep, gw + i * rstep);
            cp16(st + 3 * PLANEH + soff + i * sstep, gw + WL + i * rstep);
        }
        asm volatile("cp.async.commit_group;\n");
    }

    const int arow = (lane & 15);
    const int acol = (lane >> 4) * 8;
    const int brow = (lane & 7) + ((lane >> 4) << 3);
    const int bcol = ((lane >> 3) & 1) * 8;

    for (int c = 0; c < NCHUNK; ++c) {
        asm volatile("cp.async.wait_group 0;\n" ::: "memory");
        __syncthreads();

        // issue chunk c+1 into other buffer (its previous consumer finished pre-barrier)
        if (c + 1 < NCHUNK) {
            __half* st = smh + ((c + 1) & 1) * STAGEH;
            const int ko = (c + 1) * BK;
            #pragma unroll
            for (int i = 0; i < 2; i++) {
                cp16(st + soff + i * sstep,              gx + ko + i * rstep);
                cp16(st + PLANEH + soff + i * sstep,     gx + XL + ko + i * rstep);
                cp16(st + 2 * PLANEH + soff + i * sstep, gw + ko + i * rstep);
                cp16(st + 3 * PLANEH + soff + i * sstep, gw + WL + ko + i * rstep);
            }
            asm volatile("cp.async.commit_group;\n");
        }

        // consume chunk c: 2 k16-steps
        const __half* st = smh + (c & 1) * STAGEH;
        #pragma unroll
        for (int ks = 0; ks < 2; ++ks) {
            const int kh = ks * 16;
            uint32_t bh[2][4], bl[2][4];
            #pragma unroll
            for (int nip = 0; nip < 2; nip++) {
                const int n0 = wn * 32 + nip * 16;
                ldsm4(bh[nip], st + 2 * PLANEH + (n0 + brow) * PKH + kh + bcol);
                ldsm4(bl[nip], st + 3 * PLANEH + (n0 + brow) * PKH + kh + bcol);
            }
            #pragma unroll
            for (int mi = 0; mi < 4; mi++) {
                const int r0 = wm * 64 + mi * 16;
                uint32_t ah[4], al[4];
                ldsm4(ah, st + (r0 + arow) * PKH + kh + acol);
                ldsm4(al, st + PLANEH + (r0 + arow) * PKH + kh + acol);
                #pragma unroll
                for (int ni = 0; ni < 4; ni++) {
                    const uint32_t* pbh = &bh[ni >> 1][(ni & 1) * 2];
                    const uint32_t* pbl = &bl[ni >> 1][(ni & 1) * 2];
                    mma_f16(acc[mi][ni], al, pbh);   // small terms first
                    mma_f16(acc[mi][ni], ah, pbl);
                    mma_f16(acc[mi][ni], ah, pbh);
                }
            }
        }
    }

    // epilogue: u = acc/32 + bias
    #pragma unroll
    for (int mi = 0; mi < 4; mi++) {
        const int row0 = bm + wm * 64 + mi * 16 + (lane >> 2);
        #pragma unroll
        for (int ni = 0; ni < 4; ni++) {
            const int col = bn + wn * 32 + ni * 8 + (lane & 3) * 2;
            const float b0 = __ldg(bias + col), b1 = __ldg(bias + col + 1);
            float* o1 = g_u + (size_t)row0 * N_COLS + col;
            float* o2 = g_u + (size_t)(row0 + 8) * N_COLS + col;
            o1[0] = acc[mi][ni][0] * W_SCALE_INV + b0;
            o1[1] = acc[mi][ni][1] * W_SCALE_INV + b1;
            o2[0] = acc[mi][ni][2] * W_SCALE_INV + b0;
            o2[1] = acc[mi][ni][3] * W_SCALE_INV + b1;
        }
    }
}

// ------------------------------ Routing ------------------------------
#define RT 512
#define RW (RT / 32)   // 16 warps

__device__ __forceinline__ float warp_sum(float v) {
    #pragma unroll
    for (int o = 16; o; o >>= 1) v += __shfl_xor_sync(0xffffffffu, v, o);
    return v;
}
__device__ __forceinline__ float warp_max(float v) {
    #pragma unroll
    for (int o = 16; o; o >>= 1) v = fmaxf(v, __shfl_xor_sync(0xffffffffu, v, o));
    return v;
}
__device__ __forceinline__ float block_sum(float v, float* red, int lane, int warp) {
    v = warp_sum(v);
    __syncthreads();
    if (lane == 0) red[warp] = v;
    __syncthreads();
    float t = 0.f;
    #pragma unroll
    for (int w = 0; w < RW; w++) t += red[w];
    return t;
}
__device__ __forceinline__ float block_max(float v, float* red, int lane, int warp) {
    v = warp_max(v);
    __syncthreads();
    if (lane == 0) red[warp] = v;
    __syncthreads();
    float t = -3.0e38f;
    #pragma unroll
    for (int w = 0; w < RW; w++) t = fmaxf(t, red[w]);
    return t;
}

// One CTA (512 thr) per batch row b. Routing identical across A=8 -> compute once.
__global__ void __launch_bounds__(RT)
routing_kernel(float* __restrict__ out)
{
    const int b = blockIdx.x;
    const int tid = threadIdx.x;
    const int lane = tid & 31, warp = tid >> 5;
    __shared__ float red[RW];
    __shared__ float redc[RW][12];
    __shared__ float sv[1024];

    float u[12][2];
    const float* up = g_u + (size_t)b * N_COLS;
    #pragma unroll
    for (int c = 0; c < 12; c++)
        #pragma unroll
        for (int j = 0; j < 2; j++)
            u[c][j] = up[c * 1024 + tid + RT * j];

    float blog[12];
    #pragma unroll
    for (int c = 0; c < 12; c++) blog[c] = 0.f;

    float s[2];
    float scale = 0.f;

    #pragma unroll
    for (int it = 0; it < 3; ++it) {
        float mx = blog[0];
        #pragma unroll
        for (int c = 1; c < 12; c++) mx = fmaxf(mx, blog[c]);
        float e[12], se = 0.f;
        #pragma unroll
        for (int c = 0; c < 12; c++) { e[c] = __expf(blog[c] - mx); se += e[c]; }
        const float inv = 1.f / se;

        #pragma unroll
        for (int j = 0; j < 2; j++) {
            float t = 0.f;
            #pragma unroll
            for (int c = 0; c < 12; c++) t += e[c] * u[c][j];
            s[j] = t * inv;
        }

        float n2p = s[0]*s[0] + s[1]*s[1];
        const float n2 = block_sum(n2p, red, lane, warp);
        const float n = sqrtf(n2);
        scale = n2 / ((1.f + n2) * (n + 1e-8f));

        if (it < 2) {
            float pd[12];
            #pragma unroll
            for (int c = 0; c < 12; c++) {
                float t = u[c][0]*s[0] + u[c][1]*s[1];
                pd[c] = warp_sum(t);
            }
            if (lane == 0) {
                #pragma unroll
                for (int c = 0; c < 12; c++) redc[warp][c] = pd[c];
            }
            __syncthreads();
            #pragma unroll
            for (int c = 0; c < 12; c++) {
                float t = 0.f;
                #pragma unroll
                for (int w = 0; w < RW; w++) t += redc[w][c];
                blog[c] += scale * t;
            }
            __syncthreads();
        }
    }

    // stage v in smem, then coalesced float4 stores for all 8 A-copies
    #pragma unroll
    for (int j = 0; j < 2; j++) sv[tid + RT * j] = scale * s[j];
    __syncthreads();
    {
        const float4* sv4 = (const float4*)sv;
        const size_t base = (size_t)b * A_SZ * DOUT;
        #pragma unroll
        for (int i = 0; i < 4; i++) {
            const int idx = tid + RT * i;           // 0..2047
            const int a = idx >> 8, q = idx & 255;
            *(float4*)(out + base + (size_t)a * DOUT + q * 4) = sv4[q];
        }
    }

    // entropy over softmax(s) along D_OUT (reference uses pre-squash s)
    float lm = fmaxf(s[0], s[1]);
    const float gm = block_max(lm, red, lane, warp);
    float ex[2], le = 0.f;
    #pragma unroll
    for (int j = 0; j < 2; j++) { ex[j] = __expf(s[j] - gm); le += ex[j]; }
    const float te = block_sum(le, red, lane, warp);
    const float invd = 1.f / (te + 1e-10f);
    float lp = 0.f;
    #pragma unroll
    for (int j = 0; j < 2; j++) {
        const float p = ex[j] * invd;
        lp += p * __logf(p + 1e-10f);
    }
    const float tp = block_sum(lp, red, lane, warp);
    if (tid == 0) {
        float H = -tp;
        H = fminf(fmaxf(H, 0.f), 10.f);
        g_ent[b] = H;
    }
}

// ------------------------------ Finalize ------------------------------
__global__ void __launch_bounds__(256)
finalize_kernel(float* __restrict__ out)
{
    __shared__ float red[8];
    const int tid = threadIdx.x;
    const int lane = tid & 31, warp = tid >> 5;
    float v = 0.f;
    for (int i = tid; i < B_SZ; i += 256) v += g_ent[i];
    v = warp_sum(v);
    __syncthreads();
    if (lane == 0) red[warp] = v;
    __syncthreads();
    float s = 0.f;
    #pragma unroll
    for (int w = 0; w < 8; w++) s += red[w];
    if (tid == 0) {
        const float mean = s / (float)B_SZ;
        const float sig = 1.f / (1.f + expf(-mean));
        out[(size_t)B_SZ * A_SZ * DOUT] = -sig * 0.4f;
    }
}

// ------------------------------ Launch ------------------------------
extern "C" void kernel_launch(void* const* d_in, const int* in_sizes, int n_in,
                              void* d_out, int out_size)
{
    const float* x    = (const float*)d_in[0];
    const float* W    = (const float*)d_in[1];
    const float* bias = (const float*)d_in[2];
    float* out = (float*)d_out;

    cudaFuncSetAttribute(gemm_fp16_kernel,
                         cudaFuncAttributeMaxDynamicSharedMemorySize, SMEM_BYTES);

    // split X and W into fp16 hi/lo planes (W scaled by 32)
    {
        __half *xh, *xl, *wh, *wl;
        cudaGetSymbolAddress((void**)&xh, g_xh);
        cudaGetSymbolAddress((void**)&xl, g_xl);
        cudaGetSymbolAddress((void**)&wh, g_wh);
        cudaGetSymbolAddress((void**)&wl, g_wl);
        const int nx4 = B_SZ * DIN / 4;
        const int nw4 = N_COLS * DIN / 4;
        split_kernel<<<(nx4 + 255) / 256, 256>>>(x, xh, xl, 1.0f, nx4);
        split_kernel<<<(nw4 + 255) / 256, 256>>>(W, wh, wl, W_SCALE, nw4);
    }

    dim3 grid(N_COLS / BN, B_SZ / BM);        // (96, 64)
    gemm_fp16_kernel<<<grid, 256, SMEM_BYTES>>>(bias);
    routing_kernel<<<B_SZ, RT>>>(out);
    finalize_kernel<<<1, 256>>>(out);
}

// round 9
// speedup vs baseline: 1.1075x; 1.1075x over previous
#include <cuda_runtime.h>
#include <cuda_fp16.h>
#include <cstdint>
#include <cstddef>

#define B_SZ   8192
#define C_SZ   12
#define DIN    1024
#define DOUT   1024
#define N_COLS (C_SZ * DOUT)   // 12288
#define A_SZ   8

// Scratch (static device allocations allowed)
__device__ float  g_u[(size_t)B_SZ * N_COLS];    // 402 MB
__device__ float  g_ent[B_SZ];
__device__ __half g_xh[(size_t)B_SZ * DIN];
__device__ __half g_xl[(size_t)B_SZ * DIN];
__device__ __half g_wh[(size_t)N_COLS * DIN];    // W * 32, hi
__device__ __half g_wl[(size_t)N_COLS * DIN];    // W * 32, lo

#define W_SCALE     32.0f
#define W_SCALE_INV 0.03125f

// ------------------------------ split precompute ------------------------------
__device__ __forceinline__ void sp1(float x, __half& h, __half& l) {
    h = __float2half_rn(x);
    l = __float2half_rn(x - __half2float(h));
}

__global__ void __launch_bounds__(256)
split_kernel(const float* __restrict__ src, __half* __restrict__ hi,
             __half* __restrict__ lo, float scale, int n4)
{
    const int i = blockIdx.x * 256 + threadIdx.x;
    if (i >= n4) return;
    const float4 v = *(const float4*)(src + (size_t)i * 4);
    __half h0,h1,h2,h3,l0,l1,l2,l3;
    sp1(v.x * scale, h0, l0); sp1(v.y * scale, h1, l1);
    sp1(v.z * scale, h2, l2); sp1(v.w * scale, h3, l3);
    __half2* hp = (__half2*)(hi + (size_t)i * 4);
    __half2* lp = (__half2*)(lo + (size_t)i * 4);
    hp[0] = __halves2half2(h0, h1); hp[1] = __halves2half2(h2, h3);
    lp[0] = __halves2half2(l0, l1); lp[1] = __halves2half2(l2, l3);
}

// ------------------------------ GEMM ------------------------------
// u[b,co] = (1/32) * sum_i (xh+xl)[b,i]*(wh+wl)[co,i] + bias[co]
// acc += xl*wh + xh*wl + xh*wh   (3x fp16 MMA, fp32 accum)
// 256 threads, 8 warps: 2(M) x 4(N), warp tile 64x32. BK=32, 2-stage, 2 CTAs/SM.
#define BM 128
#define BN 128
#define BK 32
#define NCHUNK (DIN / BK)       // 32
#define PKH 40                  // halves per row (80 B stride, LDSM conflict-free)
#define PLANEH (BM * PKH)       // 5120 halves
#define STAGEH (4 * PLANEH)     // AH, AL, BH, BL
#define SMEM_BYTES (2 * STAGEH * 2)   // 81920 B -> 2 CTAs/SM

__device__ __forceinline__ uint32_t s2u(const void* p) {
    return (uint32_t)__cvta_generic_to_shared(p);
}
__device__ __forceinline__ void cp16(const __half* s, const __half* g) {
    asm volatile("cp.async.cg.shared.global [%0], [%1], 16;\n"
                 :: "r"(s2u(s)), "l"(g));
}
__device__ __forceinline__ void ldsm4(uint32_t r[4], const __half* p) {
    asm volatile("ldmatrix.sync.aligned.m8n8.x4.shared.b16 {%0,%1,%2,%3}, [%4];"
                 : "=r"(r[0]), "=r"(r[1]), "=r"(r[2]), "=r"(r[3]) : "r"(s2u(p)));
}
__device__ __forceinline__ void mma_f16(float acc[4], const uint32_t a[4], const uint32_t* b) {
    asm volatile(
        "mma.sync.aligned.m16n8k16.row.col.f32.f16.f16.f32 "
        "{%0,%1,%2,%3}, {%4,%5,%6,%7}, {%8,%9}, {%0,%1,%2,%3};\n"
        : "+f"(acc[0]), "+f"(acc[1]), "+f"(acc[2]), "+f"(acc[3])
        : "r"(a[0]), "r"(a[1]), "r"(a[2]), "r"(a[3]), "r"(b[0]), "r"(b[1]));
}

__global__ void __launch_bounds__(256, 2)
gemm_fp16_kernel(const float* __restrict__ bias)
{
    extern __shared__ __half smh[];

    const int tid  = threadIdx.x;
    const int lane = tid & 31;
    const int warp = tid >> 5;          // 0..7
    const int wm = warp >> 2;           // 0..1 (M: 64 rows each)
    const int wn = warp & 3;            // 0..3 (N: 32 cols each)
    const int bm = blockIdx.y * BM;
    const int bn = blockIdx.x * BN;

    // producer: per plane 128 rows x 2 16B-chunks; thread -> row tid>>2 (+64), c4 = tid&3
    const int prow = tid >> 2;          // 0..63
    const int pc4  = tid & 3;           // 0..3
    const __half* gx = g_xh + (size_t)(bm + prow) * DIN + pc4 * 8;
    const __half* gw = g_wh + (size_t)(bn + prow) * DIN + pc4 * 8;
    const size_t XL = (size_t)(g_xl - g_xh);   // plane offsets in elements
    const size_t WL = (size_t)(g_wl - g_wh);
    const int soff = prow * PKH + pc4 * 8;
    const size_t rstep = (size_t)64 * DIN;
    const int sstep = 64 * PKH;

    float acc[4][4][4];
    #pragma unroll
    for (int mi = 0; mi < 4; mi++)
        #pragma unroll
        for (int ni = 0; ni < 4; ni++)
            #pragma unroll
            for (int r = 0; r < 4; r++) acc[mi][ni][r] = 0.f;

    // prologue: chunk 0 -> buffer 0
    {
        __half* st = smh;
        #pragma unroll
        for (int i = 0; i < 2; i++) {
            cp16(st + soff + i * sstep,              gx + i * rstep);
            cp16(st + PLANEH + soff + i * sstep,     gx + XL + i * rstep);
            cp16(st + 2 * PLANEH + soff + i * sstep, gw + i * rstep);
            cp16(st + 3 * PLANEH + soff + i * sstep, gw + WL + i * rstep);
        }
        asm volatile("cp.async.commit_group;\n");
    }

    const int arow = (lane & 15);
    const int acol = (lane >> 4) * 8;
    const int brow = (lane & 7) + ((lane >> 4) << 3);
    const int bcol = ((lane >> 3) & 1) * 8;

    for (int c = 0; c < NCHUNK; ++c) {
        asm volatile("cp.async.wait_group 0;\n" ::: "memory");
        __syncthreads();

        // issue chunk c+1 into other buffer
        if (c + 1 < NCHUNK) {
            __half* st = smh + ((c + 1) & 1) * STAGEH;
            const int ko = (c + 1) * BK;
            #pragma unroll
            for (int i = 0; i < 2; i++) {
                cp16(st + soff + i * sstep,              gx + ko + i * rstep);
                cp16(st + PLANEH + soff + i * sstep,     gx + XL + ko + i * rstep);
                cp16(st + 2 * PLANEH + soff + i * sstep, gw + ko + i * rstep);
                cp16(st + 3 * PLANEH + soff + i * sstep, gw + WL + ko + i * rstep);
            }
            asm volatile("cp.async.commit_group;\n");
        }

        // consume chunk c: 2 k16-steps
        const __half* st = smh + (c & 1) * STAGEH;
        #pragma unroll
        for (int ks = 0; ks < 2; ++ks) {
            const int kh = ks * 16;
            uint32_t bh[2][4], bl[2][4];
            #pragma unroll
            for (int nip = 0; nip < 2; nip++) {
                const int n0 = wn * 32 + nip * 16;
                ldsm4(bh[nip], st + 2 * PLANEH + (n0 + brow) * PKH + kh + bcol);
                ldsm4(bl[nip], st + 3 * PLANEH + (n0 + brow) * PKH + kh + bcol);
            }
            #pragma unroll
            for (int mi = 0; mi < 4; mi++) {
                const int r0 = wm * 64 + mi * 16;
                uint32_t ah[4], al[4];
                ldsm4(ah, st + (r0 + arow) * PKH + kh + acol);
                ldsm4(al, st + PLANEH + (r0 + arow) * PKH + kh + acol);
                #pragma unroll
                for (int ni = 0; ni < 4; ni++) {
                    const uint32_t* pbh = &bh[ni >> 1][(ni & 1) * 2];
                    const uint32_t* pbl = &bl[ni >> 1][(ni & 1) * 2];
                    mma_f16(acc[mi][ni], al, pbh);   // small terms first
                    mma_f16(acc[mi][ni], ah, pbl);
                    mma_f16(acc[mi][ni], ah, pbh);
                }
            }
        }
    }

    // epilogue: u = acc/32 + bias
    #pragma unroll
    for (int mi = 0; mi < 4; mi++) {
        const int row0 = bm + wm * 64 + mi * 16 + (lane >> 2);
        #pragma unroll
        for (int ni = 0; ni < 4; ni++) {
            const int col = bn + wn * 32 + ni * 8 + (lane & 3) * 2;
            const float b0 = __ldg(bias + col), b1 = __ldg(bias + col + 1);
            float* o1 = g_u + (size_t)row0 * N_COLS + col;
            float* o2 = g_u + (size_t)(row0 + 8) * N_COLS + col;
            o1[0] = acc[mi][ni][0] * W_SCALE_INV + b0;
            o1[1] = acc[mi][ni][1] * W_SCALE_INV + b1;
            o2[0] = acc[mi][ni][2] * W_SCALE_INV + b0;
            o2[1] = acc[mi][ni][3] * W_SCALE_INV + b1;
        }
    }
}

// ------------------------------ Routing ------------------------------
__device__ __forceinline__ float warp_sum(float v) {
    #pragma unroll
    for (int o = 16; o; o >>= 1) v += __shfl_xor_sync(0xffffffffu, v, o);
    return v;
}
__device__ __forceinline__ float warp_max(float v) {
    #pragma unroll
    for (int o = 16; o; o >>= 1) v = fmaxf(v, __shfl_xor_sync(0xffffffffu, v, o));
    return v;
}
__device__ __forceinline__ float block_sum(float v, float* red, int lane, int warp) {
    v = warp_sum(v);
    __syncthreads();
    if (lane == 0) red[warp] = v;
    __syncthreads();
    float t = 0.f;
    #pragma unroll
    for (int w = 0; w < 8; w++) t += red[w];
    return t;
}
__device__ __forceinline__ float block_max(float v, float* red, int lane, int warp) {
    v = warp_max(v);
    __syncthreads();
    if (lane == 0) red[warp] = v;
    __syncthreads();
    float t = -3.0e38f;
    #pragma unroll
    for (int w = 0; w < 8; w++) t = fmaxf(t, red[w]);
    return t;
}

// One CTA (256 thr) per batch row b. Thread owns 4 contiguous cols -> LDG.128.
// Routing identical across A=8 -> compute once, replicate output 8x.
__global__ void __launch_bounds__(256)
routing_kernel(float* __restrict__ out)
{
    const int b = blockIdx.x;
    const int tid = threadIdx.x;
    const int lane = tid & 31, warp = tid >> 5;
    __shared__ float red[8];
    __shared__ float redc[8][12];
    __shared__ float sv[1024];

    // 12 x LDG.128, front-batched (deep MLP)
    float4 u[12];
    const float* up = g_u + (size_t)b * N_COLS + tid * 4;
    #pragma unroll
    for (int c = 0; c < 12; c++)
        u[c] = *(const float4*)(up + c * 1024);

    float blog[12];
    #pragma unroll
    for (int c = 0; c < 12; c++) blog[c] = 0.f;

    float4 s;
    float scale = 0.f;

    #pragma unroll
    for (int it = 0; it < 3; ++it) {
        float mx = blog[0];
        #pragma unroll
        for (int c = 1; c < 12; c++) mx = fmaxf(mx, blog[c]);
        float e[12], se = 0.f;
        #pragma unroll
        for (int c = 0; c < 12; c++) { e[c] = __expf(blog[c] - mx); se += e[c]; }
        const float inv = 1.f / se;

        s.x = s.y = s.z = s.w = 0.f;
        #pragma unroll
        for (int c = 0; c < 12; c++) {
            s.x += e[c] * u[c].x; s.y += e[c] * u[c].y;
            s.z += e[c] * u[c].z; s.w += e[c] * u[c].w;
        }
        s.x *= inv; s.y *= inv; s.z *= inv; s.w *= inv;

        float n2p = s.x*s.x + s.y*s.y + s.z*s.z + s.w*s.w;
        const float n2 = block_sum(n2p, red, lane, warp);
        const float n = sqrtf(n2);
        scale = n2 / ((1.f + n2) * (n + 1e-8f));

        if (it < 2) {
            float pd[12];
            #pragma unroll
            for (int c = 0; c < 12; c++) {
                float t = u[c].x*s.x + u[c].y*s.y + u[c].z*s.z + u[c].w*s.w;
                pd[c] = warp_sum(t);
            }
            if (lane == 0) {
                #pragma unroll
                for (int c = 0; c < 12; c++) redc[warp][c] = pd[c];
            }
            __syncthreads();
            #pragma unroll
            for (int c = 0; c < 12; c++) {
                float t = 0.f;
                #pragma unroll
                for (int w = 0; w < 8; w++) t += redc[w][c];
                blog[c] += scale * t;
            }
            __syncthreads();
        }
    }

    // stage v in smem, then coalesced float4 stores for all 8 A-copies
    {
        float4 v0;
        v0.x = scale * s.x; v0.y = scale * s.y;
        v0.z = scale * s.z; v0.w = scale * s.w;
        *(float4*)(sv + tid * 4) = v0;
    }
    __syncthreads();
    {
        const float4* sv4 = (const float4*)sv;
        const size_t base = (size_t)b * A_SZ * DOUT;
        #pragma unroll
        for (int i = 0; i < 8; i++) {
            const int idx = tid + 256 * i;          // 0..2047
            const int a = idx >> 8, q = idx & 255;
            *(float4*)(out + base + (size_t)a * DOUT + q * 4) = sv4[q];
        }
    }

    // entropy over softmax(s) along D_OUT (reference uses pre-squash s)
    float lm = fmaxf(fmaxf(s.x, s.y), fmaxf(s.z, s.w));
    const float gm = block_max(lm, red, lane, warp);
    float ex[4], le = 0.f;
    ex[0] = __expf(s.x - gm); ex[1] = __expf(s.y - gm);
    ex[2] = __expf(s.z - gm); ex[3] = __expf(s.w - gm);
    #pragma unroll
    for (int j = 0; j < 4; j++) le += ex[j];
    const float te = block_sum(le, red, lane, warp);
    const float invd = 1.f / (te + 1e-10f);
    float lp = 0.f;
    #pragma unroll
    for (int j = 0; j < 4; j++) {
        const float p = ex[j] * invd;
        lp += p * __logf(p + 1e-10f);
    }
    const float tp = block_sum(lp, red, lane, warp);
    if (tid == 0) {
        float H = -tp;
        H = fminf(fmaxf(H, 0.f), 10.f);
        g_ent[b] = H;
    }
}

// ------------------------------ Finalize ------------------------------
__global__ void __launch_bounds__(256)
finalize_kernel(float* __restrict__ out)
{
    __shared__ float red[8];
    const int tid = threadIdx.x;
    const int lane = tid & 31, warp = tid >> 5;
    float v = 0.f;
    for (int i = tid; i < B_SZ; i += 256) v += g_ent[i];
    const float s = block_sum(v, red, lane, warp);
    if (tid == 0) {
        const float mean = s / (float)B_SZ;
        const float sig = 1.f / (1.f + expf(-mean));
        out[(size_t)B_SZ * A_SZ * DOUT] = -sig * 0.4f;
    }
}

// ------------------------------ Launch ------------------------------
extern "C" void kernel_launch(void* const* d_in, const int* in_sizes, int n_in,
                              void* d_out, int out_size)
{
    const float* x    = (const float*)d_in[0];
    const float* W    = (const float*)d_in[1];
    const float* bias = (const float*)d_in[2];
    float* out = (float*)d_out;

    cudaFuncSetAttribute(gemm_fp16_kernel,
                         cudaFuncAttributeMaxDynamicSharedMemorySize, SMEM_BYTES);

    // split X and W into fp16 hi/lo planes (W scaled by 32)
    {
        __half *xh, *xl, *wh, *wl;
        cudaGetSymbolAddress((void**)&xh, g_xh);
        cudaGetSymbolAddress((void**)&xl, g_xl);
        cudaGetSymbolAddress((void**)&wh, g_wh);
        cudaGetSymbolAddress((void**)&wl, g_wl);
        const int nx4 = B_SZ * DIN / 4;
        const int nw4 = N_COLS * DIN / 4;
        split_kernel<<<(nx4 + 255) / 256, 256>>>(x, xh, xl, 1.0f, nx4);
        split_kernel<<<(nw4 + 255) / 256, 256>>>(W, wh, wl, W_SCALE, nw4);
    }

    dim3 grid(N_COLS / BN, B_SZ / BM);        // (96, 64)
    gemm_fp16_kernel<<<grid, 256, SMEM_BYTES>>>(bias);
    routing_kernel<<<B_SZ, 256>>>(out);
    finalize_kernel<<<1, 256>>>(out);
}

// round 13
// speedup vs baseline: 1.1103x; 1.0025x over previous
#include <cuda_runtime.h>
#include <cuda_fp16.h>
#include <cstdint>
#include <cstddef>

#define B_SZ   8192
#define C_SZ   12
#define DIN    1024
#define DOUT   1024
#define N_COLS (C_SZ * DOUT)   // 12288
#define A_SZ   8

// Scratch (static device allocations allowed)
__device__ float  g_u[(size_t)B_SZ * N_COLS];    // 402 MB (fp32: fp16 storage fails rel_err)
__device__ float  g_ent[B_SZ];
__device__ __half g_xh[(size_t)B_SZ * DIN];
__device__ __half g_xl[(size_t)B_SZ * DIN];
__device__ __half g_wh[(size_t)N_COLS * DIN];    // W * 32, hi
__device__ __half g_wl[(size_t)N_COLS * DIN];    // W * 32, lo

#define W_SCALE     32.0f
#define W_SCALE_INV 0.03125f

// ------------------------------ split precompute ------------------------------
__device__ __forceinline__ void sp1(float x, __half& h, __half& l) {
    h = __float2half_rn(x);
    l = __float2half_rn(x - __half2float(h));
}

__global__ void __launch_bounds__(256)
split_kernel(const float* __restrict__ src, __half* __restrict__ hi,
             __half* __restrict__ lo, float scale, int n4)
{
    const int i = blockIdx.x * 256 + threadIdx.x;
    if (i >= n4) return;
    const float4 v = *(const float4*)(src + (size_t)i * 4);
    __half h0,h1,h2,h3,l0,l1,l2,l3;
    sp1(v.x * scale, h0, l0); sp1(v.y * scale, h1, l1);
    sp1(v.z * scale, h2, l2); sp1(v.w * scale, h3, l3);
    __half2* hp = (__half2*)(hi + (size_t)i * 4);
    __half2* lp = (__half2*)(lo + (size_t)i * 4);
    hp[0] = __halves2half2(h0, h1); hp[1] = __halves2half2(h2, h3);
    lp[0] = __halves2half2(l0, l1); lp[1] = __halves2half2(l2, l3);
}

// ------------------------------ GEMM ------------------------------
// u[b,co] = (1/32) * sum_i (xh+xl)[b,i]*(wh+wl)[co,i] + bias[co]
// acc += xl*wh + xh*wl + xh*wh   (3x fp16 MMA, fp32 accum)
// 256 threads, 8 warps: 2(M) x 4(N), warp tile 64x32. BK=32, 2-stage, 2 CTAs/SM.
// Inner loop sweeps ni per term so consecutive MMAs hit different accumulators.
#define BM 128
#define BN 128
#define BK 32
#define NCHUNK (DIN / BK)       // 32
#define PKH 40                  // halves per row (80 B stride, LDSM conflict-free)
#define PLANEH (BM * PKH)       // 5120 halves
#define STAGEH (4 * PLANEH)     // AH, AL, BH, BL
#define SMEM_BYTES (2 * STAGEH * 2)   // 81920 B -> 2 CTAs/SM

__device__ __forceinline__ uint32_t s2u(const void* p) {
    return (uint32_t)__cvta_generic_to_shared(p);
}
__device__ __forceinline__ void cp16(const __half* s, const __half* g) {
    asm volatile("cp.async.cg.shared.global [%0], [%1], 16;\n"
                 :: "r"(s2u(s)), "l"(g));
}
__device__ __forceinline__ void ldsm4(uint32_t r[4], const __half* p) {
    asm volatile("ldmatrix.sync.aligned.m8n8.x4.shared.b16 {%0,%1,%2,%3}, [%4];"
                 : "=r"(r[0]), "=r"(r[1]), "=r"(r[2]), "=r"(r[3]) : "r"(s2u(p)));
}
__device__ __forceinline__ void mma_f16(float acc[4], const uint32_t a[4], const uint32_t* b) {
    asm volatile(
        "mma.sync.aligned.m16n8k16.row.col.f32.f16.f16.f32 "
        "{%0,%1,%2,%3}, {%4,%5,%6,%7}, {%8,%9}, {%0,%1,%2,%3};\n"
        : "+f"(acc[0]), "+f"(acc[1]), "+f"(acc[2]), "+f"(acc[3])
        : "r"(a[0]), "r"(a[1]), "r"(a[2]), "r"(a[3]), "r"(b[0]), "r"(b[1]));
}

__global__ void __launch_bounds__(256, 2)
gemm_fp16_kernel(const float* __restrict__ bias)
{
    extern __shared__ __half smh[];

    const int tid  = threadIdx.x;
    const int lane = tid & 31;
    const int warp = tid >> 5;          // 0..7
    const int wm = warp >> 2;           // 0..1 (M: 64 rows each)
    const int wn = warp & 3;            // 0..3 (N: 32 cols each)
    const int bm = blockIdx.y * BM;
    const int bn = blockIdx.x * BN;

    // producer: per plane 128 rows x 2 16B-chunks; thread -> row tid>>2 (+64), c4 = tid&3
    const int prow = tid >> 2;          // 0..63
    const int pc4  = tid & 3;           // 0..3
    const __half* gx = g_xh + (size_t)(bm + prow) * DIN + pc4 * 8;
    const __half* gw = g_wh + (size_t)(bn + prow) * DIN + pc4 * 8;
    const size_t XL = (size_t)(g_xl - g_xh);   // plane offsets in elements
    const size_t WL = (size_t)(g_wl - g_wh);
    const int soff = prow * PKH + pc4 * 8;
    const size_t rstep = (size_t)64 * DIN;
    const int sstep = 64 * PKH;

    float acc[4][4][4];
    #pragma unroll
    for (int mi = 0; mi < 4; mi++)
        #pragma unroll
        for (int ni = 0; ni < 4; ni++)
            #pragma unroll
            for (int r = 0; r < 4; r++) acc[mi][ni][r] = 0.f;

    // prologue: chunk 0 -> buffer 0
    {
        __half* st = smh;
        #pragma unroll
        for (int i = 0; i < 2; i++) {
            cp16(st + soff + i * sstep,              gx + i * rstep);
            cp16(st + PLANEH + soff + i * sstep,     gx + XL + i * rstep);
            cp16(st + 2 * PLANEH + soff + i * sstep, gw + i * rstep);
            cp16(st + 3 * PLANEH + soff + i * sstep, gw + WL + i * rstep);
        }
        asm volatile("cp.async.commit_group;\n");
    }

    const int arow = (lane & 15);
    const int acol = (lane >> 4) * 8;
    const int brow = (lane & 7) + ((lane >> 4) << 3);
    const int bcol = ((lane >> 3) & 1) * 8;

    for (int c = 0; c < NCHUNK; ++c) {
        asm volatile("cp.async.wait_group 0;\n" ::: "memory");
        __syncthreads();

        // issue chunk c+1 into other buffer
        if (c + 1 < NCHUNK) {
            __half* st = smh + ((c + 1) & 1) * STAGEH;
            const int ko = (c + 1) * BK;
            #pragma unroll
            for (int i = 0; i < 2; i++) {
                cp16(st + soff + i * sstep,              gx + ko + i * rstep);
                cp16(st + PLANEH + soff + i * sstep,     gx + XL + ko + i * rstep);
                cp16(st + 2 * PLANEH + soff + i * sstep, gw + ko + i * rstep);
                cp16(st + 3 * PLANEH + soff + i * sstep, gw + WL + ko + i * rstep);
            }
            asm volatile("cp.async.commit_group;\n");
        }

        // consume chunk c: 2 k16-steps
        const __half* st = smh + (c & 1) * STAGEH;
        #pragma unroll
        for (int ks = 0; ks < 2; ++ks) {
            const int kh = ks * 16;
            uint32_t bh[2][4], bl[2][4];
            #pragma unroll
            for (int nip = 0; nip < 2; nip++) {
                const int n0 = wn * 32 + nip * 16;
                ldsm4(bh[nip], st + 2 * PLANEH + (n0 + brow) * PKH + kh + bcol);
                ldsm4(bl[nip], st + 3 * PLANEH + (n0 + brow) * PKH + kh + bcol);
            }
            #pragma unroll
            for (int mi = 0; mi < 4; mi++) {
                const int r0 = wm * 64 + mi * 16;
                uint32_t ah[4], al[4];
                ldsm4(ah, st + (r0 + arow) * PKH + kh + acol);
                ldsm4(al, st + PLANEH + (r0 + arow) * PKH + kh + acol);
                // term-major sweeps: consecutive MMAs target different accumulators
                // (per-acc term order unchanged: al*bh, ah*bl, ah*bh)
                #pragma unroll
                for (int ni = 0; ni < 4; ni++)
                    mma_f16(acc[mi][ni], al, &bh[ni >> 1][(ni & 1) * 2]);
                #pragma unroll
                for (int ni = 0; ni < 4; ni++)
                    mma_f16(acc[mi][ni], ah, &bl[ni >> 1][(ni & 1) * 2]);
                #pragma unroll
                for (int ni = 0; ni < 4; ni++)
                    mma_f16(acc[mi][ni], ah, &bh[ni >> 1][(ni & 1) * 2]);
            }
        }
    }

    // epilogue: u = acc/32 + bias (fp32 stores)
    #pragma unroll
    for (int mi = 0; mi < 4; mi++) {
        const int row0 = bm + wm * 64 + mi * 16 + (lane >> 2);
        #pragma unroll
        for (int ni = 0; ni < 4; ni++) {
            const int col = bn + wn * 32 + ni * 8 + (lane & 3) * 2;
            const float b0 = __ldg(bias + col), b1 = __ldg(bias + col + 1);
            float* o1 = g_u + (size_t)row0 * N_COLS + col;
            float* o2 = g_u + (size_t)(row0 + 8) * N_COLS + col;
            o1[0] = acc[mi][ni][0] * W_SCALE_INV + b0;
            o1[1] = acc[mi][ni][1] * W_SCALE_INV + b1;
            o2[0] = acc[mi][ni][2] * W_SCALE_INV + b0;
            o2[1] = acc[mi][ni][3] * W_SCALE_INV + b1;
        }
    }
}

// ------------------------------ Routing ------------------------------
__device__ __forceinline__ float warp_sum(float v) {
    #pragma unroll
    for (int o = 16; o; o >>= 1) v += __shfl_xor_sync(0xffffffffu, v, o);
    return v;
}
__device__ __forceinline__ float warp_max(float v) {
    #pragma unroll
    for (int o = 16; o; o >>= 1) v = fmaxf(v, __shfl_xor_sync(0xffffffffu, v, o));
    return v;
}
__device__ __forceinline__ float block_sum(float v, float* red, int lane, int warp) {
    v = warp_sum(v);
    __syncthreads();
    if (lane == 0) red[warp] = v;
    __syncthreads();
    float t = 0.f;
    #pragma unroll
    for (int w = 0; w < 8; w++) t += red[w];
    return t;
}
__device__ __forceinline__ float block_max(float v, float* red, int lane, int warp) {
    v = warp_max(v);
    __syncthreads();
    if (lane == 0) red[warp] = v;
    __syncthreads();
    float t = -3.0e38f;
    #pragma unroll
    for (int w = 0; w < 8; w++) t = fmaxf(t, red[w]);
    return t;
}

// One CTA (256 thr) per batch row b. Thread owns 4 contiguous cols -> LDG.128.
// Routing identical across A=8 -> compute once, replicate output 8x.
// Merged block reduction: n2 + 12 dots in one smem round (2 barriers/iter).
__global__ void __launch_bounds__(256)
routing_kernel(float* __restrict__ out)
{
    const int b = blockIdx.x;
    const int tid = threadIdx.x;
    const int lane = tid & 31, warp = tid >> 5;
    __shared__ float red[8];
    __shared__ float redc[8][13];   // [warp][0]=n2, [warp][1..12]=pd
    __shared__ float sv[1024];

    // 12 x LDG.128, front-batched (deep MLP)
    float4 u[12];
    const float* up = g_u + (size_t)b * N_COLS + tid * 4;
    #pragma unroll
    for (int c = 0; c < 12; c++)
        u[c] = *(const float4*)(up + c * 1024);

    float blog[12];
    #pragma unroll
    for (int c = 0; c < 12; c++) blog[c] = 0.f;

    float4 s;
    float scale = 0.f;

    #pragma unroll
    for (int it = 0; it < 3; ++it) {
        float mx = blog[0];
        #pragma unroll
        for (int c = 1; c < 12; c++) mx = fmaxf(mx, blog[c]);
        float e[12], se = 0.f;
        #pragma unroll
        for (int c = 0; c < 12; c++) { e[c] = __expf(blog[c] - mx); se += e[c]; }
        const float inv = 1.f / se;

        s.x = s.y = s.z = s.w = 0.f;
        #pragma unroll
        for (int c = 0; c < 12; c++) {
            s.x += e[c] * u[c].x; s.y += e[c] * u[c].y;
            s.z += e[c] * u[c].z; s.w += e[c] * u[c].w;
        }
        s.x *= inv; s.y *= inv; s.z *= inv; s.w *= inv;

        const float n2p = s.x*s.x + s.y*s.y + s.z*s.z + s.w*s.w;

        if (it < 2) {
            // merged reduction: n2 + 12 pd in one redc round
            float v13[13];
            v13[0] = warp_sum(n2p);
            #pragma unroll
            for (int c = 0; c < 12; c++) {
                float t = u[c].x*s.x + u[c].y*s.y + u[c].z*s.z + u[c].w*s.w;
                v13[c + 1] = warp_sum(t);
            }
            __syncthreads();   // protect redc reuse from previous iteration
            if (lane == 0) {
                #pragma unroll
                for (int k = 0; k < 13; k++) redc[warp][k] = v13[k];
            }
            __syncthreads();
            float n2 = 0.f;
            #pragma unroll
            for (int w = 0; w < 8; w++) n2 += redc[w][0];
            const float n = sqrtf(n2);
            scale = n2 / ((1.f + n2) * (n + 1e-8f));
            #pragma unroll
            for (int c = 0; c < 12; c++) {
                float t = 0.f;
                #pragma unroll
                for (int w = 0; w < 8; w++) t += redc[w][c + 1];
                blog[c] += scale * t;
            }
        } else {
            const float n2 = block_sum(n2p, red, lane, warp);
            const float n = sqrtf(n2);
            scale = n2 / ((1.f + n2) * (n + 1e-8f));
        }
    }

    // stage v in smem, then coalesced float4 stores for all 8 A-copies
    {
        float4 v0;
        v0.x = scale * s.x; v0.y = scale * s.y;
        v0.z = scale * s.z; v0.w = scale * s.w;
        *(float4*)(sv + tid * 4) = v0;
    }
    __syncthreads();
    {
        const float4* sv4 = (const float4*)sv;
        const size_t base = (size_t)b * A_SZ * DOUT;
        #pragma unroll
        for (int i = 0; i < 8; i++) {
            const int idx = tid + 256 * i;          // 0..2047
            const int a = idx >> 8, q = idx & 255;
            *(float4*)(out + base + (size_t)a * DOUT + q * 4) = sv4[q];
        }
    }

    // entropy over softmax(s) along D_OUT (reference uses pre-squash s)
    float lm = fmaxf(fmaxf(s.x, s.y), fmaxf(s.z, s.w));
    const float gm = block_max(lm, red, lane, warp);
    float ex[4], le = 0.f;
    ex[0] = __expf(s.x - gm); ex[1] = __expf(s.y - gm);
    ex[2] = __expf(s.z - gm); ex[3] = __expf(s.w - gm);
    #pragma unroll
    for (int j = 0; j < 4; j++) le += ex[j];
    const float te = block_sum(le, red, lane, warp);
    const float invd = 1.f / (te + 1e-10f);
    float lp = 0.f;
    #pragma unroll
    for (int j = 0; j < 4; j++) {
        const float p = ex[j] * invd;
        lp += p * __logf(p + 1e-10f);
    }
    const float tp = block_sum(lp, red, lane, warp);
    if (tid == 0) {
        float H = -tp;
        H = fminf(fmaxf(H, 0.f), 10.f);
        g_ent[b] = H;
    }
}

// ------------------------------ Finalize ------------------------------
__global__ void __launch_bounds__(256)
finalize_kernel(float* __restrict__ out)
{
    __shared__ float red[8];
    const int tid = threadIdx.x;
    const int lane = tid & 31, warp = tid >> 5;
    float v = 0.f;
    for (int i = tid; i < B_SZ; i += 256) v += g_ent[i];
    const float s = block_sum(v, red, lane, warp);
    if (tid == 0) {
        const float mean = s / (float)B_SZ;
        const float sig = 1.f / (1.f + expf(-mean));
        out[(size_t)B_SZ * A_SZ * DOUT] = -sig * 0.4f;
    }
}

// ------------------------------ Launch ------------------------------
extern "C" void kernel_launch(void* const* d_in, const int* in_sizes, int n_in,
                              void* d_out, int out_size)
{
    const float* x    = (const float*)d_in[0];
    const float* W    = (const float*)d_in[1];
    const float* bias = (const float*)d_in[2];
    float* out = (float*)d_out;

    cudaFuncSetAttribute(gemm_fp16_kernel,
                         cudaFuncAttributeMaxDynamicSharedMemorySize, SMEM_BYTES);

    // split X and W into fp16 hi/lo planes (W scaled by 32)
    {
        __half *xh, *xl, *wh, *wl;
        cudaGetSymbolAddress((void**)&xh, g_xh);
        cudaGetSymbolAddress((void**)&xl, g_xl);
        cudaGetSymbolAddress((void**)&wh, g_wh);
        cudaGetSymbolAddress((void**)&wl, g_wl);
        const int nx4 = B_SZ * DIN / 4;
        const int nw4 = N_COLS * DIN / 4;
        split_kernel<<<(nx4 + 255) / 256, 256>>>(x, xh, xl, 1.0f, nx4);
        split_kernel<<<(nw4 + 255) / 256, 256>>>(W, wh, wl, W_SCALE, nw4);
    }

    dim3 grid(N_COLS / BN, B_SZ / BM);        // (96, 64)
    gemm_fp16_kernel<<<grid, 256, SMEM_BYTES>>>(bias);
    routing_kernel<<<B_SZ, 256>>>(out);
    finalize_kernel<<<1, 256>>>(out);
}

// round 16
// speedup vs baseline: 1.2857x; 1.1580x over previous
#include <cuda_runtime.h>
#include <cuda_fp16.h>
#include <cstdint>
#include <cstddef>

#define B_SZ   8192
#define C_SZ   12
#define DIN    1024
#define DOUT   1024
#define N_COLS (C_SZ * DOUT)   // 12288
#define A_SZ   8

// Scratch (static device allocations allowed)
__device__ float  g_u[(size_t)B_SZ * N_COLS];    // 402 MB (fp32: fp16 storage fails rel_err)
__device__ float  g_ent[B_SZ];
__device__ __half g_xh[(size_t)B_SZ * DIN];
__device__ __half g_xl[(size_t)B_SZ * DIN];
__device__ __half g_wh[(size_t)N_COLS * DIN];    // W * 32, hi
__device__ __half g_wl[(size_t)N_COLS * DIN];    // W * 32, lo

#define W_SCALE     32.0f
#define W_SCALE_INV 0.03125f

// ------------------------------ split precompute ------------------------------
__device__ __forceinline__ void sp1(float x, __half& h, __half& l) {
    h = __float2half_rn(x);
    l = __float2half_rn(x - __half2float(h));
}

__global__ void __launch_bounds__(256)
split_kernel(const float* __restrict__ src, __half* __restrict__ hi,
             __half* __restrict__ lo, float scale, int n4)
{
    const int i = blockIdx.x * 256 + threadIdx.x;
    if (i >= n4) return;
    const float4 v = *(const float4*)(src + (size_t)i * 4);
    __half h0,h1,h2,h3,l0,l1,l2,l3;
    sp1(v.x * scale, h0, l0); sp1(v.y * scale, h1, l1);
    sp1(v.z * scale, h2, l2); sp1(v.w * scale, h3, l3);
    __half2* hp = (__half2*)(hi + (size_t)i * 4);
    __half2* lp = (__half2*)(lo + (size_t)i * 4);
    hp[0] = __halves2half2(h0, h1); hp[1] = __halves2half2(h2, h3);
    lp[0] = __halves2half2(l0, l1); lp[1] = __halves2half2(l2, l3);
}

// ------------------------------ GEMM ------------------------------
// u[b,co] = (1/32) * sum_i (xh+xl)[b,i]*(wh+wl)[co,i] + bias[co]
// acc += xl*wh + xh*wl + xh*wh   (3x fp16 MMA, fp32 accum)
// 256 threads, 8 warps: 2(M) x 4(N), warp tile 64x32.
// BK=32, 3-stage cp.async pipeline, XOR-swizzled smem (no padding), 2 CTAs/SM.
#define BM 128
#define BN 128
#define BK 32
#define NCHUNK (DIN / BK)       // 32
#define STAGES 3
#define PLANEH (BM * BK)        // 4096 halves per plane (64 B rows, swizzled)
#define STAGEH (4 * PLANEH)     // AH, AL, BH, BL = 16384 halves = 32768 B
#define SMEM_BYTES (STAGES * STAGEH * 2)   // 98304 B -> 2 CTAs/SM

// swizzled offset (halves): row has 4 x 16B chunks; chunk' = chunk ^ ((row>>1)&3)
// Each 8-row LDSM phase -> 8 distinct 16B slots mod 128B (conflict-free).
__device__ __forceinline__ int sw_off(int row, int ch) {
    return (row << 5) + ((ch ^ ((row >> 1) & 3)) << 3);
}

__device__ __forceinline__ uint32_t s2u(const void* p) {
    return (uint32_t)__cvta_generic_to_shared(p);
}
__device__ __forceinline__ void cp16(const __half* s, const __half* g) {
    asm volatile("cp.async.cg.shared.global [%0], [%1], 16;\n"
                 :: "r"(s2u(s)), "l"(g));
}
__device__ __forceinline__ void ldsm4(uint32_t r[4], const __half* p) {
    asm volatile("ldmatrix.sync.aligned.m8n8.x4.shared.b16 {%0,%1,%2,%3}, [%4];"
                 : "=r"(r[0]), "=r"(r[1]), "=r"(r[2]), "=r"(r[3]) : "r"(s2u(p)));
}
__device__ __forceinline__ void mma_f16(float acc[4], const uint32_t a[4], const uint32_t* b) {
    asm volatile(
        "mma.sync.aligned.m16n8k16.row.col.f32.f16.f16.f32 "
        "{%0,%1,%2,%3}, {%4,%5,%6,%7}, {%8,%9}, {%0,%1,%2,%3};\n"
        : "+f"(acc[0]), "+f"(acc[1]), "+f"(acc[2]), "+f"(acc[3])
        : "r"(a[0]), "r"(a[1]), "r"(a[2]), "r"(a[3]), "r"(b[0]), "r"(b[1]));
}

__global__ void __launch_bounds__(256, 2)
gemm_fp16_kernel(const float* __restrict__ bias)
{
    extern __shared__ __half smh[];

    const int tid  = threadIdx.x;
    const int lane = tid & 31;
    const int warp = tid >> 5;          // 0..7
    const int wm = warp >> 2;           // 0..1 (M: 64 rows each)
    const int wn = warp & 3;            // 0..3 (N: 32 cols each)
    const int bm = blockIdx.y * BM;
    const int bn = blockIdx.x * BN;

    // producer: per plane 128 rows x 4 16B-chunks; thread -> row tid>>2 (+64), chunk tid&3
    const int prow = tid >> 2;          // 0..63
    const int pch  = tid & 3;           // chunk 0..3
    const __half* gx = g_xh + (size_t)(bm + prow) * DIN + pch * 8;
    const __half* gw = g_wh + (size_t)(bn + prow) * DIN + pch * 8;
    const size_t XL = (size_t)(g_xl - g_xh);   // plane offsets in elements
    const size_t WL = (size_t)(g_wl - g_wh);
    const int so0 = sw_off(prow, pch);
    const int so1 = sw_off(prow + 64, pch);
    const size_t rstep = (size_t)64 * DIN;

    float acc[4][4][4];
    #pragma unroll
    for (int mi = 0; mi < 4; mi++)
        #pragma unroll
        for (int ni = 0; ni < 4; ni++)
            #pragma unroll
            for (int r = 0; r < 4; r++) acc[mi][ni][r] = 0.f;

    // prologue: chunks 0,1 -> stages 0,1
    #pragma unroll
    for (int c = 0; c < STAGES - 1; ++c) {
        __half* st = smh + c * STAGEH;
        const int ko = c * BK;
        cp16(st + so0,              gx + ko);
        cp16(st + so1,              gx + ko + rstep);
        cp16(st + PLANEH + so0,     gx + XL + ko);
        cp16(st + PLANEH + so1,     gx + XL + ko + rstep);
        cp16(st + 2 * PLANEH + so0, gw + ko);
        cp16(st + 2 * PLANEH + so1, gw + ko + rstep);
        cp16(st + 3 * PLANEH + so0, gw + WL + ko);
        cp16(st + 3 * PLANEH + so1, gw + WL + ko + rstep);
        asm volatile("cp.async.commit_group;\n");
    }

    // consumer per-lane fragment coordinates
    const int arow = lane & 15;             // + r0
    const int ach  = lane >> 4;             // + ks*2
    const int brow = (lane & 7) + ((lane >> 4) << 3);   // + n0
    const int bch  = (lane >> 3) & 1;       // + ks*2

    int sb_c = 0;   // stage holding chunk c
    for (int c = 0; c < NCHUNK; ++c) {
        asm volatile("cp.async.wait_group 1;\n" ::: "memory");
        __syncthreads();

        // issue chunk c+2 into stage (sb_c + 2) % 3  (== stage of chunk c-1, already consumed)
        if (c + STAGES - 1 < NCHUNK) {
            int sbn = sb_c + STAGES - 1; if (sbn >= STAGES) sbn -= STAGES;
            __half* st = smh + sbn * STAGEH;
            const int ko = (c + STAGES - 1) * BK;
            cp16(st + so0,              gx + ko);
            cp16(st + so1,              gx + ko + rstep);
            cp16(st + PLANEH + so0,     gx + XL + ko);
            cp16(st + PLANEH + so1,     gx + XL + ko + rstep);
            cp16(st + 2 * PLANEH + so0, gw + ko);
            cp16(st + 2 * PLANEH + so1, gw + ko + rstep);
            cp16(st + 3 * PLANEH + so0, gw + WL + ko);
            cp16(st + 3 * PLANEH + so1, gw + WL + ko + rstep);
            asm volatile("cp.async.commit_group;\n");
        }

        // consume chunk c: 2 k16-steps
        const __half* st = smh + sb_c * STAGEH;
        #pragma unroll
        for (int ks = 0; ks < 2; ++ks) {
            uint32_t bh[2][4], bl[2][4];
            #pragma unroll
            for (int nip = 0; nip < 2; nip++) {
                const int r = wn * 32 + nip * 16 + brow;
                const int o = sw_off(r, ks * 2 + bch);
                ldsm4(bh[nip], st + 2 * PLANEH + o);
                ldsm4(bl[nip], st + 3 * PLANEH + o);
            }
            #pragma unroll
            for (int mi = 0; mi < 4; mi++) {
                const int r = wm * 64 + mi * 16 + arow;
                const int o = sw_off(r, ks * 2 + ach);
                uint32_t ah[4], al[4];
                ldsm4(ah, st + o);
                ldsm4(al, st + PLANEH + o);
                #pragma unroll
                for (int ni = 0; ni < 4; ni++)
                    mma_f16(acc[mi][ni], al, &bh[ni >> 1][(ni & 1) * 2]);
                #pragma unroll
                for (int ni = 0; ni < 4; ni++)
                    mma_f16(acc[mi][ni], ah, &bl[ni >> 1][(ni & 1) * 2]);
                #pragma unroll
                for (int ni = 0; ni < 4; ni++)
                    mma_f16(acc[mi][ni], ah, &bh[ni >> 1][(ni & 1) * 2]);
            }
        }
        if (++sb_c == STAGES) sb_c = 0;
    }

    // epilogue: u = acc/32 + bias (fp32 stores)
    #pragma unroll
    for (int mi = 0; mi < 4; mi++) {
        const int row0 = bm + wm * 64 + mi * 16 + (lane >> 2);
        #pragma unroll
        for (int ni = 0; ni < 4; ni++) {
            const int col = bn + wn * 32 + ni * 8 + (lane & 3) * 2;
            const float b0 = __ldg(bias + col), b1 = __ldg(bias + col + 1);
            float* o1 = g_u + (size_t)row0 * N_COLS + col;
            float* o2 = g_u + (size_t)(row0 + 8) * N_COLS + col;
            o1[0] = acc[mi][ni][0] * W_SCALE_INV + b0;
            o1[1] = acc[mi][ni][1] * W_SCALE_INV + b1;
            o2[0] = acc[mi][ni][2] * W_SCALE_INV + b0;
            o2[1] = acc[mi][ni][3] * W_SCALE_INV + b1;
        }
    }
}

// ------------------------------ Routing ------------------------------
__device__ __forceinline__ float warp_sum(float v) {
    #pragma unroll
    for (int o = 16; o; o >>= 1) v += __shfl_xor_sync(0xffffffffu, v, o);
    return v;
}
__device__ __forceinline__ float warp_max(float v) {
    #pragma unroll
    for (int o = 16; o; o >>= 1) v = fmaxf(v, __shfl_xor_sync(0xffffffffu, v, o));
    return v;
}
__device__ __forceinline__ float block_sum(float v, float* red, int lane, int warp) {
    v = warp_sum(v);
    __syncthreads();
    if (lane == 0) red[warp] = v;
    __syncthreads();
    float t = 0.f;
    #pragma unroll
    for (int w = 0; w < 8; w++) t += red[w];
    return t;
}
__device__ __forceinline__ float block_max(float v, float* red, int lane, int warp) {
    v = warp_max(v);
    __syncthreads();
    if (lane == 0) red[warp] = v;
    __syncthreads();
    float t = -3.0e38f;
    #pragma unroll
    for (int w = 0; w < 8; w++) t = fmaxf(t, red[w]);
    return t;
}

// One CTA (256 thr) per batch row b. Thread owns 4 contiguous cols -> LDG.128.
// Routing identical across A=8 -> compute once, replicate output 8x.
// Merged block reduction: n2 + 12 dots in one smem round (2 barriers/iter).
__global__ void __launch_bounds__(256)
routing_kernel(float* __restrict__ out)
{
    const int b = blockIdx.x;
    const int tid = threadIdx.x;
    const int lane = tid & 31, warp = tid >> 5;
    __shared__ float red[8];
    __shared__ float redc[8][13];   // [warp][0]=n2, [warp][1..12]=pd
    __shared__ float sv[1024];

    // 12 x LDG.128, front-batched (deep MLP)
    float4 u[12];
    const float* up = g_u + (size_t)b * N_COLS + tid * 4;
    #pragma unroll
    for (int c = 0; c < 12; c++)
        u[c] = *(const float4*)(up + c * 1024);

    float blog[12];
    #pragma unroll
    for (int c = 0; c < 12; c++) blog[c] = 0.f;

    float4 s;
    float scale = 0.f;

    #pragma unroll
    for (int it = 0; it < 3; ++it) {
        float mx = blog[0];
        #pragma unroll
        for (int c = 1; c < 12; c++) mx = fmaxf(mx, blog[c]);
        float e[12], se = 0.f;
        #pragma unroll
        for (int c = 0; c < 12; c++) { e[c] = __expf(blog[c] - mx); se += e[c]; }
        const float inv = 1.f / se;

        s.x = s.y = s.z = s.w = 0.f;
        #pragma unroll
        for (int c = 0; c < 12; c++) {
            s.x += e[c] * u[c].x; s.y += e[c] * u[c].y;
            s.z += e[c] * u[c].z; s.w += e[c] * u[c].w;
        }
        s.x *= inv; s.y *= inv; s.z *= inv; s.w *= inv;

        const float n2p = s.x*s.x + s.y*s.y + s.z*s.z + s.w*s.w;

        if (it < 2) {
            // merged reduction: n2 + 12 pd in one redc round
            float v13[13];
            v13[0] = warp_sum(n2p);
            #pragma unroll
            for (int c = 0; c < 12; c++) {
                float t = u[c].x*s.x + u[c].y*s.y + u[c].z*s.z + u[c].w*s.w;
                v13[c + 1] = warp_sum(t);
            }
            __syncthreads();   // protect redc reuse from previous iteration
            if (lane == 0) {
                #pragma unroll
                for (int k = 0; k < 13; k++) redc[warp][k] = v13[k];
            }
            __syncthreads();
            float n2 = 0.f;
            #pragma unroll
            for (int w = 0; w < 8; w++) n2 += redc[w][0];
            const float n = sqrtf(n2);
            scale = n2 / ((1.f + n2) * (n + 1e-8f));
            #pragma unroll
            for (int c = 0; c < 12; c++) {
                float t = 0.f;
                #pragma unroll
                for (int w = 0; w < 8; w++) t += redc[w][c + 1];
                blog[c] += scale * t;
            }
        } else {
            const float n2 = block_sum(n2p, red, lane, warp);
            const float n = sqrtf(n2);
            scale = n2 / ((1.f + n2) * (n + 1e-8f));
        }
    }

    // stage v in smem, then coalesced float4 stores for all 8 A-copies
    {
        float4 v0;
        v0.x = scale * s.x; v0.y = scale * s.y;
        v0.z = scale * s.z; v0.w = scale * s.w;
        *(float4*)(sv + tid * 4) = v0;
    }
    __syncthreads();
    {
        const float4* sv4 = (const float4*)sv;
        const size_t base = (size_t)b * A_SZ * DOUT;
        #pragma unroll
        for (int i = 0; i < 8; i++) {
            const int idx = tid + 256 * i;          // 0..2047
            const int a = idx >> 8, q = idx & 255;
            *(float4*)(out + base + (size_t)a * DOUT + q * 4) = sv4[q];
        }
    }

    // entropy over softmax(s) along D_OUT (reference uses pre-squash s)
    float lm = fmaxf(fmaxf(s.x, s.y), fmaxf(s.z, s.w));
    const float gm = block_max(lm, red, lane, warp);
    float ex[4], le = 0.f;
    ex[0] = __expf(s.x - gm); ex[1] = __expf(s.y - gm);
    ex[2] = __expf(s.z - gm); ex[3] = __expf(s.w - gm);
    #pragma unroll
    for (int j = 0; j < 4; j++) le += ex[j];
    const float te = block_sum(le, red, lane, warp);
    const float invd = 1.f / (te + 1e-10f);
    float lp = 0.f;
    #pragma unroll
    for (int j = 0; j < 4; j++) {
        const float p = ex[j] * invd;
        lp += p * __logf(p + 1e-10f);
    }
    const float tp = block_sum(lp, red, lane, warp);
    if (tid == 0) {
        float H = -tp;
        H = fminf(fmaxf(H, 0.f), 10.f);
        g_ent[b] = H;
    }
}

// ------------------------------ Finalize ------------------------------
__global__ void __launch_bounds__(256)
finalize_kernel(float* __restrict__ out)
{
    __shared__ float red[8];
    const int tid = threadIdx.x;
    const int lane = tid & 31, warp = tid >> 5;
    float v = 0.f;
    for (int i = tid; i < B_SZ; i += 256) v += g_ent[i];
    const float s = block_sum(v, red, lane, warp);
    if (tid == 0) {
        const float mean = s / (float)B_SZ;
        const float sig = 1.f / (1.f + expf(-mean));
        out[(size_t)B_SZ * A_SZ * DOUT] = -sig * 0.4f;
    }
}

// ------------------------------ Launch ------------------------------
extern "C" void kernel_launch(void* const* d_in, const int* in_sizes, int n_in,
                              void* d_out, int out_size)
{
    const float* x    = (const float*)d_in[0];
    const float* W    = (const float*)d_in[1];
    const float* bias = (const float*)d_in[2];
    float* out = (float*)d_out;

    cudaFuncSetAttribute(gemm_fp16_kernel,
                         cudaFuncAttributeMaxDynamicSharedMemorySize, SMEM_BYTES);

    // split X and W into fp16 hi/lo planes (W scaled by 32)
    {
        __half *xh, *xl, *wh, *wl;
        cudaGetSymbolAddress((void**)&xh, g_xh);
        cudaGetSymbolAddress((void**)&xl, g_xl);
        cudaGetSymbolAddress((void**)&wh, g_wh);
        cudaGetSymbolAddress((void**)&wl, g_wl);
        const int nx4 = B_SZ * DIN / 4;
        const int nw4 = N_COLS * DIN / 4;
        split_kernel<<<(nx4 + 255) / 256, 256>>>(x, xh, xl, 1.0f, nx4);
        split_kernel<<<(nw4 + 255) / 256, 256>>>(W, wh, wl, W_SCALE, nw4);
    }

    dim3 grid(N_COLS / BN, B_SZ / BM);        // (96, 64)
    gemm_fp16_kernel<<<grid, 256, SMEM_BYTES>>>(bias);
    routing_kernel<<<B_SZ, 256>>>(out);
    finalize_kernel<<<1, 256>>>(out);
}